// round 10
// baseline (speedup 1.0000x reference)
#include <cuda_runtime.h>
#include <cstdint>

// BumpKNN R9: 3xTF32 mma.sync.m16n8k8, m32 per warp (B-fragment reuse),
// 4 independent accumulation chains per n-group, finalize fused via
// last-CTA arrival counter.

#define NQ      2048
#define ND      65536
#define STRIPS  8           // 2048 / 256 queries per CTA
#define SPLITS  18          // 8*18 = 144 CTAs ~ one wave
#define NTILE   128         // points per smem tile
#define THREADS 256
#define KPAD    20          // floats per point row: conflict-free LDS

__device__ float g_partial[SPLITS * NQ];
__device__ unsigned int g_done;   // zero-init; reset by last CTA each run

__device__ __forceinline__ uint32_t f2tf(float x) {
    uint32_t r; asm("cvt.rna.tf32.f32 %0, %1;" : "=r"(r) : "f"(x)); return r;
}

__device__ __forceinline__ void mma8(float c[4], const uint32_t a[4],
                                     uint32_t b0, uint32_t b1) {
    asm("mma.sync.aligned.m16n8k8.row.col.f32.tf32.tf32.f32 "
        "{%0,%1,%2,%3}, {%4,%5,%6,%7}, {%8,%9}, {%0,%1,%2,%3};"
        : "+f"(c[0]), "+f"(c[1]), "+f"(c[2]), "+f"(c[3])
        : "r"(a[0]), "r"(a[1]), "r"(a[2]), "r"(a[3]), "r"(b0), "r"(b1));
}

// ---------------------------------------------------------------------------
__global__ void __launch_bounds__(THREADS, 1)
mma_kernel(const float* __restrict__ x, const float* __restrict__ data,
           float* __restrict__ out) {
    __shared__ __align__(16) float sBhi[2][NTILE][KPAD];
    __shared__ __align__(16) float sBlo[2][NTILE][KPAD];
    __shared__ __align__(8)  float sD2[2][NTILE];

    const int tid = threadIdx.x, lane = tid & 31, w = tid >> 5;
    const int strip = blockIdx.x, split = blockIdx.y;
    const int tiles = (split < 8) ? 29 : 28;       // 8*29 + 10*28 = 512 tiles
    const int tbase = (split < 8) ? 29 * split : 232 + 28 * (split - 8);

    const int g4 = lane >> 2, kc = lane & 3;
    const int qb = strip * 256 + w * 32;           // 32 query rows per warp

    // A fragments: -2*x tf32 hi/lo, rowblock rb (16 rows) x k-chunk c.
    uint32_t ah[2][2][4], al[2][2][4];
#pragma unroll
    for (int rb = 0; rb < 2; rb++)
#pragma unroll
        for (int c = 0; c < 2; c++)
#pragma unroll
            for (int j = 0; j < 4; j++) {
                int row = qb + rb * 16 + g4 + (j & 1) * 8;
                int k   = c * 8 + kc + (j >> 1) * 4;
                float s = -2.f * __ldg(&x[(size_t)row * 16 + k]);
                uint32_t h = f2tf(s);
                ah[rb][c][j] = h;
                al[rb][c][j] = f2tf(s - __uint_as_float(h));
            }

    const float4* dv = reinterpret_cast<const float4*>(data);
    const bool loader = tid < NTILE;
    float4 r0, r1, r2, r3;

    auto stash = [&](int buf) {
        float v[16] = {r0.x, r0.y, r0.z, r0.w, r1.x, r1.y, r1.z, r1.w,
                       r2.x, r2.y, r2.z, r2.w, r3.x, r3.y, r3.z, r3.w};
        float d2 = 0.f;
        uint32_t hi[16], lo[16];
#pragma unroll
        for (int i = 0; i < 16; i++) {
            d2 = fmaf(v[i], v[i], d2);
            hi[i] = f2tf(v[i]);
            lo[i] = f2tf(v[i] - __uint_as_float(hi[i]));
        }
        uint4* ph = reinterpret_cast<uint4*>(&sBhi[buf][tid][0]);
        uint4* pl = reinterpret_cast<uint4*>(&sBlo[buf][tid][0]);
#pragma unroll
        for (int b = 0; b < 4; b++) {
            ph[b] = make_uint4(hi[4*b], hi[4*b+1], hi[4*b+2], hi[4*b+3]);
            pl[b] = make_uint4(lo[4*b], lo[4*b+1], lo[4*b+2], lo[4*b+3]);
        }
        sD2[buf][tid] = d2;
    };

    if (loader) {
        size_t p = (size_t)tbase * NTILE + tid;
        r0 = dv[p*4+0]; r1 = dv[p*4+1]; r2 = dv[p*4+2]; r3 = dv[p*4+3];
        stash(0);
    }
    __syncthreads();

    const float INF = 3.402823466e38f;
    float mn[8] = {INF, INF, INF, INF, INF, INF, INF, INF};

    for (int t = 0; t < tiles; t++) {
        const int buf = t & 1;
        if (t + 1 < tiles && loader) {            // prefetch next tile
            size_t p = (size_t)(tbase + t + 1) * NTILE + tid;
            r0 = dv[p*4+0]; r1 = dv[p*4+1]; r2 = dv[p*4+2]; r3 = dv[p*4+3];
        }

        const float* bh_ = &sBhi[buf][0][0];
        const float* bl_ = &sBlo[buf][0][0];
        const float* d2_ = &sD2[buf][0];
#pragma unroll 8
        for (int it = 0; it < NTILE / 8; it++) {   // 16 n8 groups
            const int nb = it * 8;
            const uint32_t* rh = reinterpret_cast<const uint32_t*>(bh_ + (nb + g4) * KPAD);
            const uint32_t* rl = reinterpret_cast<const uint32_t*>(bl_ + (nb + g4) * KPAD);
            uint32_t bh0 = rh[kc],     bh1 = rh[kc + 4];
            uint32_t bh2 = rh[kc + 8], bh3 = rh[kc + 12];
            uint32_t bl0 = rl[kc],     bl1 = rl[kc + 4];
            uint32_t bl2 = rl[kc + 8], bl3 = rl[kc + 12];

            float2 dd = *reinterpret_cast<const float2*>(d2_ + nb + 2 * kc);

            // 4 independent chains: [rowblock][kchunk]; d2 folded into k0 init.
            float c00[4] = {dd.x, dd.y, dd.x, dd.y};
            float c10[4] = {dd.x, dd.y, dd.x, dd.y};
            float c01[4] = {0.f, 0.f, 0.f, 0.f};
            float c11[4] = {0.f, 0.f, 0.f, 0.f};

            mma8(c00, ah[0][0], bh0, bh1);  mma8(c10, ah[1][0], bh0, bh1);
            mma8(c01, ah[0][1], bh2, bh3);  mma8(c11, ah[1][1], bh2, bh3);
            mma8(c00, ah[0][0], bl0, bl1);  mma8(c10, ah[1][0], bl0, bl1);
            mma8(c01, ah[0][1], bl2, bl3);  mma8(c11, ah[1][1], bl2, bl3);
            mma8(c00, al[0][0], bh0, bh1);  mma8(c10, al[1][0], bh0, bh1);
            mma8(c01, al[0][1], bh2, bh3);  mma8(c11, al[1][1], bh2, bh3);

#pragma unroll
            for (int i = 0; i < 4; i++) {
                mn[i]     = fminf(mn[i],     c00[i] + c01[i]);
                mn[4 + i] = fminf(mn[4 + i], c10[i] + c11[i]);
            }
        }

        if (t + 1 < tiles && loader) stash((t + 1) & 1);
        __syncthreads();
    }

    // Per-rowblock row mins; reduce across the 4 kc-lanes sharing each row.
#pragma unroll
    for (int rb = 0; rb < 2; rb++) {
        float rA = fminf(mn[rb * 4 + 0], mn[rb * 4 + 1]);
        float rB = fminf(mn[rb * 4 + 2], mn[rb * 4 + 3]);
        rA = fminf(rA, __shfl_xor_sync(0xffffffffu, rA, 1));
        rA = fminf(rA, __shfl_xor_sync(0xffffffffu, rA, 2));
        rB = fminf(rB, __shfl_xor_sync(0xffffffffu, rB, 1));
        rB = fminf(rB, __shfl_xor_sync(0xffffffffu, rB, 2));
        if (kc == 0) {
            int q = qb + rb * 16 + g4;
            g_partial[split * NQ + q]     = rA;   // = min(d2 - 2*dot)
            g_partial[split * NQ + q + 8] = rB;
        }
    }

    // ---- fused finalize: last CTA to arrive does the bump epilogue ----
    __threadfence();
    __shared__ unsigned int sLast;
    __syncthreads();
    if (tid == 0) sLast = atomicAdd(&g_done, 1u);
    __syncthreads();
    if (sLast == STRIPS * SPLITS - 1) {
        __threadfence();
        for (int q = tid; q < NQ; q += THREADS) {
            const float4* xp = reinterpret_cast<const float4*>(x + (size_t)q * 16);
            float4 a = xp[0], b = xp[1], c = xp[2], d = xp[3];
            float x2 = a.x*a.x + a.y*a.y + a.z*a.z + a.w*a.w
                     + b.x*b.x + b.y*b.y + b.z*b.z + b.w*b.w
                     + c.x*c.x + c.y*c.y + c.z*c.z + c.w*c.w
                     + d.x*d.x + d.y*d.y + d.z*d.z + d.w*d.w;
            float m = INF;
#pragma unroll
            for (int s = 0; s < SPLITS; s++)
                m = fminf(m, g_partial[s * NQ + q]);

            float nn2  = fmaxf(x2 + m, 0.0f);          // clamp tiny negatives
            float d2c  = fmaxf(nn2, 1e-12f);
            float dist = sqrtf(d2c);
            float r = 0.0f;
            if (dist < 2.0f) {                          // RADIUS = 2
                float ds = dist * dist;                 // reference sqrt->square
                r = expf(1.0f / (ds - 4.0f) + 0.25f);   // DECAY/denom + DECAY/r^2
            }
            out[q] = r;
        }
        __syncthreads();
        if (tid == 0) g_done = 0;                       // reset for next replay
    }
}

// ---------------------------------------------------------------------------
extern "C" void kernel_launch(void* const* d_in, const int* in_sizes, int n_in,
                              void* d_out, int out_size) {
    const float* x    = (const float*)d_in[0];
    const float* data = (const float*)d_in[1];
    if (n_in >= 2 && in_sizes[0] > in_sizes[1]) {  // defensive order check
        x    = (const float*)d_in[1];
        data = (const float*)d_in[0];
    }

    dim3 grid(STRIPS, SPLITS);
    mma_kernel<<<grid, THREADS>>>(x, data, (float*)d_out);
}